// round 14
// baseline (speedup 1.0000x reference)
#include <cuda_runtime.h>
#include <cuda_bf16.h>
#include <math.h>
#include <complex>
#include <algorithm>

// Problem: RS=[(16,0),(16,1)] -> N_DIM=64, N_PATH=1536, RADIAL_H=64
// points = 16*32*32 = 16384; out = points * 64*64 fp32.

#define NPOINTS 16384
#define GPTS    16
#define NBLK    (NPOINTS / GPTS)
#define NPATH   1536
#define NTHREADS 512

struct Consts {
    float cg000;
    float cg011[3][3];   // real3j(0,1,1)[0][j][k]
    float cg101[3][3];   // real3j(1,0,1)[i][0][k]
    float cg110[3][3];   // real3j(1,1,0)[i][j][0]
    float cg111[3][3][3];
    float cg112[3][3][5];
    float nrm[2][2][2];
};

// W2 permuted, NO duplication (384 KB), k-quad float4 per (ph, kq, sl, tc):
//   float index o = ((ph*48 + kq*3 + sl)*256 + tc)*4 + e
//   k = kq*4 + e ; s = 3*ph + sl ; col(s,tc) = s<3 ? s*256+tc : 768+3*tc+(s-3)
__device__ float g_W2P[64 * NPATH];

__global__ void permute_w2(const float* __restrict__ W2) {
    int o = blockIdx.x * blockDim.x + threadIdx.x;
    if (o >= 64 * NPATH) return;
    int e    = o & 3;
    int tc   = (o >> 2) & 255;
    int slot = o >> 10;          // 0..95
    int sl   = slot % 3;
    int kq   = (slot / 3) % 16;
    int ph   = slot / 48;
    int k    = kq * 4 + e;
    int s    = 3 * ph + sl;
    int col  = (s < 3) ? (s * 256 + tc) : (768 + 3 * tc + (s - 3));
    g_W2P[o] = W2[k * NPATH + col];
}

__device__ __forceinline__ unsigned long long fma2(unsigned long long a,
                                                   unsigned long long b,
                                                   unsigned long long c) {
    unsigned long long d;
    asm("fma.rn.f32x2 %0, %1, %2, %3;" : "=l"(d) : "l"(a), "l"(b), "l"(c));
    return d;
}
__device__ __forceinline__ unsigned long long pack2same(float v) {
    unsigned long long d;
    asm("mov.b64 %0, {%1, %1};" : "=l"(d) : "f"(v));
    return d;
}
__device__ __forceinline__ void unpack2(unsigned long long v, float& lo, float& hi) {
    asm("mov.b64 {%0, %1}, %2;" : "=f"(lo), "=f"(hi) : "l"(v));
}
__device__ __forceinline__ void stg_cs(float4* p, float4 v) {
    asm volatile("st.global.cs.v4.f32 [%0], {%1, %2, %3, %4};"
                 :: "l"(p), "f"(v.x), "f"(v.y), "f"(v.z), "f"(v.w) : "memory");
}

// Dynamic smem layout (bytes):
//   [0, 98304)        sR: float[6][16][256]   ((s*16+p)*256 + tc)
//   [98304, 102400)   sh_h: float[64][16]
//   [102400, 104704)  sh_pp: float[16][36]
//   [104704, 104768)  sh_rad: float[16]
#define OFF_H   98304
#define OFF_PP  102400
#define OFF_RAD 104704
#define SMEM_TOTAL 104768

__global__ __launch_bounds__(NTHREADS, 1)
void qm9_fused(const float* __restrict__ r,
               const float* __restrict__ W1,
               const float* __restrict__ b1,
               const float* __restrict__ b2,
               float* __restrict__ out,
               const Consts C)
{
    extern __shared__ __align__(16) char smem[];
    float* sR          = (float*)smem;                  // [(s*16+p)*256 + tc]
    float (*sh_h)[16]  = (float(*)[16])(smem + OFF_H);
    float (*sh_pp)[36] = (float(*)[36])(smem + OFF_PP);
    float* sh_rad      = (float*)(smem + OFF_RAD);

    const int t  = threadIdx.x;
    const int tc = t & 255;      // column owner
    const int ph = t >> 8;       // s-half: owns s in {3ph, 3ph+1, 3ph+2}
    const int block0 = blockIdx.x * GPTS;

    // ---- Phase A: per-point SH + folded CG*Y*norm (threads 0..15) ----
    if (t < GPTS) {
        int pg = block0 + t;
        float x = r[pg * 3 + 0], y = r[pg * 3 + 1], z = r[pg * 3 + 2];
        float r2 = x * x + y * y + z * z;
        sh_rad[t] = sqrtf(r2);
        float inv  = rsqrtf(r2);
        float inv2 = 1.0f / r2;
        const float c0  = 0.28209479177387814f;
        const float c1  = 0.48860251190291992f;
        const float c2  = 1.09254843059207907f;
        const float c20 = 0.31539156525252005f;
        float Y[9];
        Y[0] = c0;
        Y[1] = c1 * y * inv;
        Y[2] = c1 * z * inv;
        Y[3] = c1 * x * inv;
        Y[4] = c2 * x * y * inv2;
        Y[5] = c2 * y * z * inv2;
        Y[6] = c20 * (3.0f * z * z - r2) * inv2;
        Y[7] = c2 * x * z * inv2;
        Y[8] = 0.5f * c2 * (x * x - y * y) * inv2;

        int zf = (r2 == 0.0f) ? 1 : 0;
        float s00 = C.nrm[0][0][zf], s01 = C.nrm[0][1][zf];
        float s10 = C.nrm[1][0][zf], s11 = C.nrm[1][1][zf];

        sh_pp[t][0] = C.cg000 * Y[0] * s00;
        #pragma unroll
        for (int j = 0; j < 3; j++) {
            float a = 0.f;
            #pragma unroll
            for (int k = 0; k < 3; k++) a += C.cg011[j][k] * Y[1 + k];
            sh_pp[t][1 + j] = a * s01;
        }
        #pragma unroll
        for (int i = 0; i < 3; i++) {
            float a = 0.f;
            #pragma unroll
            for (int k = 0; k < 3; k++) a += C.cg101[i][k] * Y[1 + k];
            sh_pp[t][4 + i] = a * s10;
        }
        #pragma unroll
        for (int i = 0; i < 3; i++) {
            #pragma unroll
            for (int j = 0; j < 3; j++) {
                sh_pp[t][7 + i * 3 + j] = C.cg110[i][j] * Y[0] * s11;
                float a1 = 0.f;
                #pragma unroll
                for (int k = 0; k < 3; k++) a1 += C.cg111[i][j][k] * Y[1 + k];
                sh_pp[t][16 + i * 3 + j] = a1 * s11;
                float a2 = 0.f;
                #pragma unroll
                for (int k = 0; k < 5; k++) a2 += C.cg112[i][j][k] * Y[4 + k];
                sh_pp[t][25 + i * 3 + j] = a2 * s11;
            }
        }
    }
    __syncthreads();

    // ---- Phase B: h = silu(rad*W1+b1), plain float [k][p] ----
    {
        int p  = t & 15;
        int k0 = (t >> 4) * 2;   // t>>4 in 0..31 -> k0 in 0..62
        float rad = sh_rad[p];
        #pragma unroll
        for (int e = 0; e < 2; e++) {
            float xx = fmaf(rad, W1[k0 + e], b1[k0 + e]);
            sh_h[k0 + e][p] = xx / (1.0f + expf(-xx));
        }
    }

    // b2 loads hoisted here to hide their latency under Phase B/barrier.
    float b2v[3];
    #pragma unroll
    for (int sl = 0; sl < 3; sl++) {
        int s = 3 * ph + sl;
        b2v[sl] = b2[(s < 3) ? (s * 256 + tc) : (768 + 3 * tc + (s - 3))];
    }
    __syncthreads();

    // ---- Phase C: f32x2 GEMM over point-pairs, 2-deep weight prefetch ----
    unsigned long long acc[8][3];   // acc[pr][sl] = (R_s(2pr), R_s(2pr+1))
    #pragma unroll
    for (int pr = 0; pr < 8; pr++)
        #pragma unroll
        for (int sl = 0; sl < 3; sl++) acc[pr][sl] = 0ull;

    const float4* w4 = (const float4*)g_W2P + (ph * 48) * 256 + tc;

    float4 a0 = w4[(0 * 3 + 0) * 256], a1 = w4[(0 * 3 + 1) * 256], a2 = w4[(0 * 3 + 2) * 256];
    float4 n0 = w4[(1 * 3 + 0) * 256], n1 = w4[(1 * 3 + 1) * 256], n2 = w4[(1 * 3 + 2) * 256];

    #pragma unroll 1
    for (int kq = 0; kq < 16; kq++) {
        int kn = (kq + 2 < 16) ? (kq + 2) : 15;
        float4 f0 = w4[(kn * 3 + 0) * 256];
        float4 f1 = w4[(kn * 3 + 1) * 256];
        float4 f2 = w4[(kn * 3 + 2) * 256];

        #pragma unroll
        for (int e = 0; e < 4; e++) {
            int k = kq * 4 + e;
            const ulonglong2* h2 = (const ulonglong2*)&sh_h[k][0];
            ulonglong2 hA = h2[0];
            ulonglong2 hB = h2[1];
            ulonglong2 hC = h2[2];
            ulonglong2 hD = h2[3];

            float w0 = ((const float*)&a0)[e];
            float w1 = ((const float*)&a1)[e];
            float w2 = ((const float*)&a2)[e];
            unsigned long long wd0 = pack2same(w0);
            unsigned long long wd1 = pack2same(w1);
            unsigned long long wd2 = pack2same(w2);

            acc[0][0] = fma2(hA.x, wd0, acc[0][0]);
            acc[0][1] = fma2(hA.x, wd1, acc[0][1]);
            acc[0][2] = fma2(hA.x, wd2, acc[0][2]);
            acc[1][0] = fma2(hA.y, wd0, acc[1][0]);
            acc[1][1] = fma2(hA.y, wd1, acc[1][1]);
            acc[1][2] = fma2(hA.y, wd2, acc[1][2]);
            acc[2][0] = fma2(hB.x, wd0, acc[2][0]);
            acc[2][1] = fma2(hB.x, wd1, acc[2][1]);
            acc[2][2] = fma2(hB.x, wd2, acc[2][2]);
            acc[3][0] = fma2(hB.y, wd0, acc[3][0]);
            acc[3][1] = fma2(hB.y, wd1, acc[3][1]);
            acc[3][2] = fma2(hB.y, wd2, acc[3][2]);
            acc[4][0] = fma2(hC.x, wd0, acc[4][0]);
            acc[4][1] = fma2(hC.x, wd1, acc[4][1]);
            acc[4][2] = fma2(hC.x, wd2, acc[4][2]);
            acc[5][0] = fma2(hC.y, wd0, acc[5][0]);
            acc[5][1] = fma2(hC.y, wd1, acc[5][1]);
            acc[5][2] = fma2(hC.y, wd2, acc[5][2]);
            acc[6][0] = fma2(hD.x, wd0, acc[6][0]);
            acc[6][1] = fma2(hD.x, wd1, acc[6][1]);
            acc[6][2] = fma2(hD.x, wd2, acc[6][2]);
            acc[7][0] = fma2(hD.y, wd0, acc[7][0]);
            acc[7][1] = fma2(hD.y, wd1, acc[7][1]);
            acc[7][2] = fma2(hD.y, wd2, acc[7][2]);
        }
        a0 = n0; a1 = n1; a2 = n2;
        n0 = f0; n1 = f1; n2 = f2;
    }

    // ---- Exchange: write R (+b2) for this thread's 3 s over all 16 points ----
    #pragma unroll
    for (int pr = 0; pr < 8; pr++) {
        #pragma unroll
        for (int sl = 0; sl < 3; sl++) {
            float lo, hi;
            unpack2(acc[pr][sl], lo, hi);
            int s = 3 * ph + sl;
            sR[(s * 16 + 2 * pr + 0) * 256 + tc] = lo + b2v[sl];
            sR[(s * 16 + 2 * pr + 1) * 256 + tc] = hi + b2v[sl];
        }
    }
    __syncthreads();   // the single epilogue barrier

    // ---- Phase D: coalesced store phase (thread handles points ph*8..ph*8+7) ----
    const int tu = tc >> 4;     // 0..15
    const int c  = tc & 15;     // col chunk

    // c>=4 path constants: vd takes exactly two values (vd0, vd0+1).
    int vd0 = 0, vd3 = 0, jd0 = 0, jd1 = 0, jd2 = 0, jd3 = 0;
    bool sel1 = true, sel2 = true;  // true -> use lo (vd0)
    if (c >= 4) {
        int base = 4 * (c - 4);
        vd0 = base / 3;             jd0 = base - 3 * vd0;
        int vd1 = (base + 1) / 3;   jd1 = (base + 1) - 3 * vd1;
        int vd2 = (base + 2) / 3;   jd2 = (base + 2) - 3 * vd2;
        vd3 = (base + 3) / 3;       jd3 = (base + 3) - 3 * vd3;
        sel1 = (vd1 == vd0);
        sel2 = (vd2 == vd0);
    }
    int um[4], im[4];
    #pragma unroll
    for (int m = 1; m < 4; m++) {
        int rr = (m - 1) * 16 + tu;
        um[m] = rr / 3;
        im[m] = rr - 3 * um[m];
    }

    #pragma unroll 2
    for (int j = 0; j < 8; j++) {
        const int p = ph * 8 + j;
        const float* pp = sh_pp[p];
        float* o = out + (size_t)(block0 + p) * 4096;
        float4* o4 = (float4*)o;

        if (c < 4) {
            // Batch the 4 wide loads, then scale+store.
            float4 L0 = *(const float4*)&sR[(0 * 16 + p) * 256 + tu * 16 + 4 * c];
            float4 L1 = *(const float4*)&sR[(2 * 16 + p) * 256 + um[1] * 16 + 4 * c];
            float4 L2 = *(const float4*)&sR[(2 * 16 + p) * 256 + um[2] * 16 + 4 * c];
            float4 L3 = *(const float4*)&sR[(2 * 16 + p) * 256 + um[3] * 16 + 4 * c];
            float sc0 = pp[0];
            float sc1 = pp[4 + im[1]];
            float sc2 = pp[4 + im[2]];
            float sc3 = pp[4 + im[3]];
            stg_cs(o4 + 0 * 256 + tc, make_float4(sc0 * L0.x, sc0 * L0.y, sc0 * L0.z, sc0 * L0.w));
            stg_cs(o4 + 1 * 256 + tc, make_float4(sc1 * L1.x, sc1 * L1.y, sc1 * L1.z, sc1 * L1.w));
            stg_cs(o4 + 2 * 256 + tc, make_float4(sc2 * L2.x, sc2 * L2.y, sc2 * L2.z, sc2 * L2.w));
            stg_cs(o4 + 3 * 256 + tc, make_float4(sc3 * L3.x, sc3 * L3.y, sc3 * L3.z, sc3 * L3.w));
        } else {
            // Batched dedup loads: 2 per array (lo at vd0, hi at vd0+1).
            const float* s1b = &sR[(1 * 16 + p) * 256 + tu * 16];
            float s1lo = s1b[vd0], s1hi = s1b[vd3];

            float lo3[3][3], hi3[3][3];   // [m-1][arr 0..2 = s3,s4,s5]
            #pragma unroll
            for (int m = 1; m < 4; m++) {
                int u2 = um[m];
                const float* b3 = &sR[(3 * 16 + p) * 256 + u2 * 16];
                const float* b4 = &sR[(4 * 16 + p) * 256 + u2 * 16];
                const float* b5 = &sR[(5 * 16 + p) * 256 + u2 * 16];
                lo3[m - 1][0] = b3[vd0]; hi3[m - 1][0] = b3[vd3];
                lo3[m - 1][1] = b4[vd0]; hi3[m - 1][1] = b4[vd3];
                lo3[m - 1][2] = b5[vd0]; hi3[m - 1][2] = b5[vd3];
            }

            // m = 0
            {
                float v0 = pp[1 + jd0] * s1lo;
                float v1 = pp[1 + jd1] * (sel1 ? s1lo : s1hi);
                float v2 = pp[1 + jd2] * (sel2 ? s1lo : s1hi);
                float v3 = pp[1 + jd3] * s1hi;
                stg_cs(o4 + 0 * 256 + tc, make_float4(v0, v1, v2, v3));
            }
            // m = 1..3
            #pragma unroll
            for (int m = 1; m < 4; m++) {
                int i = im[m];
                const float* pa = pp + 7  + 3 * i;
                const float* pb = pp + 16 + 3 * i;
                const float* pc = pp + 25 + 3 * i;
                float a3 = lo3[m - 1][0], A3 = hi3[m - 1][0];
                float a4 = lo3[m - 1][1], A4 = hi3[m - 1][1];
                float a5 = lo3[m - 1][2], A5 = hi3[m - 1][2];
                float s3e1 = sel1 ? a3 : A3, s4e1 = sel1 ? a4 : A4, s5e1 = sel1 ? a5 : A5;
                float s3e2 = sel2 ? a3 : A3, s4e2 = sel2 ? a4 : A4, s5e2 = sel2 ? a5 : A5;
                float v0 = pa[jd0] * a3   + pb[jd0] * a4   + pc[jd0] * a5;
                float v1 = pa[jd1] * s3e1 + pb[jd1] * s4e1 + pc[jd1] * s5e1;
                float v2 = pa[jd2] * s3e2 + pb[jd2] * s4e2 + pc[jd2] * s5e2;
                float v3 = pa[jd3] * A3   + pb[jd3] * A4   + pc[jd3] * A5;
                stg_cs(o4 + m * 256 + tc, make_float4(v0, v1, v2, v3));
            }
        }
    }
}

// ===========================================================================
// Host: exact replication of the reference real-3j / norm constants.
// ===========================================================================
static double dfact_(int n) { double r = 1.0; for (int i = 2; i <= n; i++) r *= i; return r; }

static double su2_cg_(int j1, int m1, int j2, int m2, int j3, int m3) {
    if (m3 != m1 + m2) return 0.0;
    int vmin = std::max(std::max(-j1 + j2 + m3, -j1 + m1), 0);
    int vmax = std::min(std::min(j2 + j3 + m1, j3 - j1 + j2), j3 + m3);
    double c = sqrt((2 * j3 + 1) * dfact_(j3 + j1 - j2) * dfact_(j3 - j1 + j2) *
                    dfact_(j1 + j2 - j3) / dfact_(j1 + j2 + j3 + 1)) *
               sqrt(dfact_(j3 + m3) * dfact_(j3 - m3) /
                    (dfact_(j1 + m1) * dfact_(j1 - m1) * dfact_(j2 + m2) * dfact_(j2 - m2)));
    double s = 0.0;
    for (int v = vmin; v <= vmax; v++) {
        double sg = ((v + j2 + m2) & 1) ? -1.0 : 1.0;
        s += sg * dfact_(j2 + j3 + m1 - v) * dfact_(j1 - m1 + v) /
             (dfact_(v) * dfact_(j3 - j1 + j2 - v) * dfact_(j3 + m3 - v) *
              dfact_(v + j1 - j2 - m3));
    }
    return c * s;
}

static void Qmat_(int l, std::complex<double> q[5][5]) {
    for (int i = 0; i < 5; i++) for (int j = 0; j < 5; j++) q[i][j] = 0.0;
    q[l][l] = 1.0;
    double s2 = 1.0 / sqrt(2.0);
    for (int m = 1; m <= l; m++) {
        double pm = (m & 1) ? -1.0 : 1.0;
        q[l + m][l - m] = s2;
        q[l + m][l + m] = pm * s2;
        q[l - m][l - m] = std::complex<double>(0.0, s2);
        q[l - m][l + m] = std::complex<double>(0.0, -pm * s2);
    }
}

static void real3j_(int l1, int l2, int l3, double outc[5][5][5]) {
    int d1 = 2 * l1 + 1, d2 = 2 * l2 + 1, d3 = 2 * l3 + 1;
    double w[5][5][5];
    for (int i = 0; i < 5; i++) for (int j = 0; j < 5; j++) for (int k = 0; k < 5; k++)
        w[i][j][k] = 0.0;
    for (int m1 = -l1; m1 <= l1; m1++)
        for (int m2 = -l2; m2 <= l2; m2++) {
            int m3 = -(m1 + m2);
            if (m3 < -l3 || m3 > l3) continue;
            double sg = ((l1 - l2 + m1 + m2) & 1) ? -1.0 : 1.0;
            w[m1 + l1][m2 + l2][m3 + l3] =
                sg / sqrt((double)(2 * l3 + 1)) * su2_cg_(l1, m1, l2, m2, l3, -m3);
        }
    std::complex<double> q1[5][5], q2[5][5], q3[5][5];
    Qmat_(l1, q1); Qmat_(l2, q2); Qmat_(l3, q3);
    std::complex<double> Cc[5][5][5];
    for (int a = 0; a < d1; a++)
        for (int b = 0; b < d2; b++)
            for (int c = 0; c < d3; c++) {
                std::complex<double> s = 0.0;
                for (int i = 0; i < d1; i++)
                    for (int j = 0; j < d2; j++)
                        for (int k = 0; k < d3; k++)
                            s += q1[a][i] * q2[b][j] * q3[c][k] * w[i][j][k];
                Cc[a][b][c] = s;
            }
    double maxv = 0.0;
    for (int a = 0; a < d1; a++) for (int b = 0; b < d2; b++) for (int c = 0; c < d3; c++)
        maxv = std::max(maxv, std::abs(Cc[a][b][c]));
    std::complex<double> ph = 0.0;
    for (int a = 0; a < d1 && ph == 0.0; a++)
        for (int b = 0; b < d2 && ph == 0.0; b++)
            for (int c = 0; c < d3 && ph == 0.0; c++)
                if (std::abs(Cc[a][b][c]) >= maxv * (1.0 - 1e-9)) ph = Cc[a][b][c];
    for (int i = 0; i < 5; i++) for (int j = 0; j < 5; j++) for (int k = 0; k < 5; k++)
        outc[i][j][k] = 0.0;
    if (std::abs(ph) < 1e-12) {
        for (int a = 0; a < d1; a++) for (int b = 0; b < d2; b++) for (int c = 0; c < d3; c++)
            outc[a][b][c] = Cc[a][b][c].real();
    } else {
        std::complex<double> u = ph / std::abs(ph);
        for (int a = 0; a < d1; a++) for (int b = 0; b < d2; b++) for (int c = 0; c < d3; c++)
            outc[a][b][c] = (Cc[a][b][c] / u).real();
    }
}

extern "C" void kernel_launch(void* const* d_in, const int* in_sizes, int n_in,
                              void* d_out, int out_size) {
    const float* r  = (const float*)d_in[0];
    const float* W1 = (const float*)d_in[1];
    const float* b1 = (const float*)d_in[2];
    const float* W2 = (const float*)d_in[3];
    const float* b2 = (const float*)d_in[4];
    float* out = (float*)d_out;

    Consts C;
    double tmp[5][5][5];
    real3j_(0, 0, 0, tmp); C.cg000 = (float)tmp[0][0][0];
    real3j_(0, 1, 1, tmp);
    for (int j = 0; j < 3; j++) for (int k = 0; k < 3; k++) C.cg011[j][k] = (float)tmp[0][j][k];
    real3j_(1, 0, 1, tmp);
    for (int i = 0; i < 3; i++) for (int k = 0; k < 3; k++) C.cg101[i][k] = (float)tmp[i][0][k];
    real3j_(1, 1, 0, tmp);
    for (int i = 0; i < 3; i++) for (int j = 0; j < 3; j++) C.cg110[i][j] = (float)tmp[i][j][0];
    real3j_(1, 1, 1, tmp);
    for (int i = 0; i < 3; i++) for (int j = 0; j < 3; j++) for (int k = 0; k < 3; k++)
        C.cg111[i][j][k] = (float)tmp[i][j][k];
    real3j_(1, 1, 2, tmp);
    for (int i = 0; i < 3; i++) for (int j = 0; j < 3; j++) for (int k = 0; k < 5; k++)
        C.cg112[i][j][k] = (float)tmp[i][j][k];

    const double fourpi = 4.0 * M_PI;
    double nse[2] = {32.0, 64.0};
    for (int i = 0; i < 2; i++)
        for (int j = 0; j < 2; j++) {
            double li = (j == 0) ? 0.0 : 1.0;
            double lm = sqrt(2.0 * li + 1.0) * sqrt(fourpi);
            C.nrm[i][j][0] = (float)(lm / sqrt(nse[i]));
            C.nrm[i][j][1] = (float)(lm / sqrt(16.0));
        }

    cudaFuncSetAttribute(qm9_fused, cudaFuncAttributeMaxDynamicSharedMemorySize,
                         SMEM_TOTAL);

    permute_w2<<<(64 * NPATH + 255) / 256, 256>>>(W2);
    qm9_fused<<<NBLK, NTHREADS, SMEM_TOTAL>>>(r, W1, b1, b2, out, C);
}

// round 15
// speedup vs baseline: 1.0453x; 1.0453x over previous
#include <cuda_runtime.h>
#include <cuda_bf16.h>
#include <math.h>
#include <complex>
#include <algorithm>

// Problem: RS=[(16,0),(16,1)] -> N_DIM=64, N_PATH=1536, RADIAL_H=64
// points = 16*32*32 = 16384; out = points * 64*64 fp32.

#define NPOINTS 16384
#define GPTS    8
#define NBLK    (NPOINTS / GPTS)
#define NPATH   1536
#define NTHREADS 256

struct Consts {
    float cg000;
    float cg011[3][3];   // real3j(0,1,1)[0][j][k]
    float cg101[3][3];   // real3j(1,0,1)[i][0][k]
    float cg110[3][3];   // real3j(1,1,0)[i][j][0]
    float cg111[3][3][3];
    float cg112[3][3][5];
    float nrm[2][2][2];
};

// W2 permuted, NO duplication (384 KB), k-quad float4 per (ph, kq, sl, tc):
//   float index o = ((ph*48 + kq*3 + sl)*256 + tc)*4 + e
//   k = kq*4 + e ; s = 3*ph + sl ; col(s,tc) = s<3 ? s*256+tc : 768+3*tc+(s-3)
__device__ float g_W2P[64 * NPATH];

__global__ void permute_w2(const float* __restrict__ W2) {
    int o = blockIdx.x * blockDim.x + threadIdx.x;
    if (o >= 64 * NPATH) return;
    int e    = o & 3;
    int tc   = (o >> 2) & 255;
    int slot = o >> 10;          // 0..95
    int sl   = slot % 3;
    int kq   = (slot / 3) % 16;
    int ph   = slot / 48;
    int k    = kq * 4 + e;
    int s    = 3 * ph + sl;
    int col  = (s < 3) ? (s * 256 + tc) : (768 + 3 * tc + (s - 3));
    g_W2P[o] = W2[k * NPATH + col];
}

__device__ __forceinline__ unsigned long long fma2(unsigned long long a,
                                                   unsigned long long b,
                                                   unsigned long long c) {
    unsigned long long d;
    asm("fma.rn.f32x2 %0, %1, %2, %3;" : "=l"(d) : "l"(a), "l"(b), "l"(c));
    return d;
}
__device__ __forceinline__ unsigned long long pack2same(float v) {
    unsigned long long d;
    asm("mov.b64 %0, {%1, %1};" : "=l"(d) : "f"(v));
    return d;
}
__device__ __forceinline__ void unpack2(unsigned long long v, float& lo, float& hi) {
    asm("mov.b64 {%0, %1}, %2;" : "=f"(lo), "=f"(hi) : "l"(v));
}
__device__ __forceinline__ void stg_cs(float4* p, float4 v) {
    asm volatile("st.global.cs.v4.f32 [%0], {%1, %2, %3, %4};"
                 :: "l"(p), "f"(v.x), "f"(v.y), "f"(v.z), "f"(v.w) : "memory");
}

// Dynamic smem layout (bytes), per 256-thread CTA (8 points):
//   [0, 49152)       sR: float[6][8][256]   ((s*8+p)*256 + tc)
//   [49152, 51200)   sh_h: float[64][8]
//   [51200, 52352)   sh_pp: float[8][36]
//   [52352, 52384)   sh_rad: float[8]
#define OFF_H   49152
#define OFF_PP  51200
#define OFF_RAD 52352
#define SMEM_TOTAL 52384

__global__ __launch_bounds__(NTHREADS, 2)
void qm9_fused(const float* __restrict__ r,
               const float* __restrict__ W1,
               const float* __restrict__ b1,
               const float* __restrict__ b2,
               float* __restrict__ out,
               const Consts C)
{
    extern __shared__ __align__(16) char smem[];
    float* sR          = (float*)smem;                  // [(s*8+p)*256 + tc]
    float (*sh_h)[8]   = (float(*)[8])(smem + OFF_H);
    float (*sh_pp)[36] = (float(*)[36])(smem + OFF_PP);
    float* sh_rad      = (float*)(smem + OFF_RAD);

    const int t = threadIdx.x;   // 0..255 — column owner, owns ALL 6 s
    const int block0 = blockIdx.x * GPTS;

    // ---- Phase A: per-point SH + folded CG*Y*norm (threads 0..7) ----
    if (t < GPTS) {
        int pg = block0 + t;
        float x = r[pg * 3 + 0], y = r[pg * 3 + 1], z = r[pg * 3 + 2];
        float r2 = x * x + y * y + z * z;
        sh_rad[t] = sqrtf(r2);
        float inv  = rsqrtf(r2);
        float inv2 = 1.0f / r2;
        const float c0  = 0.28209479177387814f;
        const float c1  = 0.48860251190291992f;
        const float c2  = 1.09254843059207907f;
        const float c20 = 0.31539156525252005f;
        float Y[9];
        Y[0] = c0;
        Y[1] = c1 * y * inv;
        Y[2] = c1 * z * inv;
        Y[3] = c1 * x * inv;
        Y[4] = c2 * x * y * inv2;
        Y[5] = c2 * y * z * inv2;
        Y[6] = c20 * (3.0f * z * z - r2) * inv2;
        Y[7] = c2 * x * z * inv2;
        Y[8] = 0.5f * c2 * (x * x - y * y) * inv2;

        int zf = (r2 == 0.0f) ? 1 : 0;
        float s00 = C.nrm[0][0][zf], s01 = C.nrm[0][1][zf];
        float s10 = C.nrm[1][0][zf], s11 = C.nrm[1][1][zf];

        sh_pp[t][0] = C.cg000 * Y[0] * s00;
        #pragma unroll
        for (int j = 0; j < 3; j++) {
            float a = 0.f;
            #pragma unroll
            for (int k = 0; k < 3; k++) a += C.cg011[j][k] * Y[1 + k];
            sh_pp[t][1 + j] = a * s01;
        }
        #pragma unroll
        for (int i = 0; i < 3; i++) {
            float a = 0.f;
            #pragma unroll
            for (int k = 0; k < 3; k++) a += C.cg101[i][k] * Y[1 + k];
            sh_pp[t][4 + i] = a * s10;
        }
        #pragma unroll
        for (int i = 0; i < 3; i++) {
            #pragma unroll
            for (int j = 0; j < 3; j++) {
                sh_pp[t][7 + i * 3 + j] = C.cg110[i][j] * Y[0] * s11;
                float a1 = 0.f;
                #pragma unroll
                for (int k = 0; k < 3; k++) a1 += C.cg111[i][j][k] * Y[1 + k];
                sh_pp[t][16 + i * 3 + j] = a1 * s11;
                float a2 = 0.f;
                #pragma unroll
                for (int k = 0; k < 5; k++) a2 += C.cg112[i][j][k] * Y[4 + k];
                sh_pp[t][25 + i * 3 + j] = a2 * s11;
            }
        }
    }
    __syncthreads();

    // ---- Phase B: h = silu(rad*W1+b1), plain float [k][p] ----
    {
        int p  = t & 7;
        int k0 = (t >> 3) * 2;   // t>>3 in 0..31 -> k0 in 0..62
        float rad = sh_rad[p];
        #pragma unroll
        for (int e = 0; e < 2; e++) {
            float xx = fmaf(rad, W1[k0 + e], b1[k0 + e]);
            sh_h[k0 + e][p] = xx / (1.0f + expf(-xx));
        }
    }

    // b2 loads hoisted (hidden under Phase B + barrier).
    float b2v[6];
    #pragma unroll
    for (int s = 0; s < 6; s++)
        b2v[s] = b2[(s < 3) ? (s * 256 + t) : (768 + 3 * t + (s - 3))];
    __syncthreads();

    // ---- Phase C: f32x2 GEMM over point-pairs; thread owns all 6 s-cols.
    unsigned long long acc[4][6];   // acc[pr][s] = (R_s(2pr), R_s(2pr+1))
    #pragma unroll
    for (int pr = 0; pr < 4; pr++)
        #pragma unroll
        for (int s = 0; s < 6; s++) acc[pr][s] = 0ull;

    const float4* w4 = (const float4*)g_W2P + t;
    // slot(s, kq) = ((s>=3 ? 48 : 0) + kq*3 + s%3) * 256

    float4 aw[6];
    #pragma unroll
    for (int s = 0; s < 6; s++)
        aw[s] = w4[(((s >= 3) ? 48 : 0) + 0 * 3 + (s % 3)) * 256];

    #pragma unroll 1
    for (int kq = 0; kq < 16; kq++) {
        int kn = (kq + 1 < 16) ? (kq + 1) : 15;
        float4 nw[6];
        #pragma unroll
        for (int s = 0; s < 6; s++)
            nw[s] = w4[(((s >= 3) ? 48 : 0) + kn * 3 + (s % 3)) * 256];

        #pragma unroll
        for (int e = 0; e < 4; e++) {
            int k = kq * 4 + e;
            const ulonglong2* h2 = (const ulonglong2*)&sh_h[k][0];
            ulonglong2 hA = h2[0];   // points 0,1 | 2,3
            ulonglong2 hB = h2[1];   // points 4,5 | 6,7
            #pragma unroll
            for (int s = 0; s < 6; s++) {
                unsigned long long wd = pack2same(((const float*)&aw[s])[e]);
                acc[0][s] = fma2(hA.x, wd, acc[0][s]);
                acc[1][s] = fma2(hA.y, wd, acc[1][s]);
                acc[2][s] = fma2(hB.x, wd, acc[2][s]);
                acc[3][s] = fma2(hB.y, wd, acc[3][s]);
            }
        }
        #pragma unroll
        for (int s = 0; s < 6; s++) aw[s] = nw[s];
    }

    // ---- Exchange: write R (+b2) for all 6 s over 8 points ----
    #pragma unroll
    for (int pr = 0; pr < 4; pr++) {
        #pragma unroll
        for (int s = 0; s < 6; s++) {
            float lo, hi;
            unpack2(acc[pr][s], lo, hi);
            sR[(s * 8 + 2 * pr + 0) * 256 + t] = lo + b2v[s];
            sR[(s * 8 + 2 * pr + 1) * 256 + t] = hi + b2v[s];
        }
    }
    __syncthreads();   // single epilogue barrier

    // ---- Phase D: coalesced store phase (R13 body, 8 points) ----
    const int tu = t >> 4;      // 0..15
    const int c  = t & 15;      // col chunk

    int vd0 = 0, vd1 = 0, vd2 = 0, vd3 = 0, jd0 = 0, jd1 = 0, jd2 = 0, jd3 = 0;
    if (c >= 4) {
        int base = 4 * (c - 4);
        vd0 = (base + 0) / 3; jd0 = (base + 0) - 3 * vd0;
        vd1 = (base + 1) / 3; jd1 = (base + 1) - 3 * vd1;
        vd2 = (base + 2) / 3; jd2 = (base + 2) - 3 * vd2;
        vd3 = (base + 3) / 3; jd3 = (base + 3) - 3 * vd3;
    }
    int um[4], im[4];
    #pragma unroll
    for (int m = 1; m < 4; m++) {
        int rr = (m - 1) * 16 + tu;
        um[m] = rr / 3;
        im[m] = rr - 3 * um[m];
    }

    #pragma unroll 1
    for (int p = 0; p < GPTS; p++) {
        const float* pp = sh_pp[p];
        float* o = out + (size_t)(block0 + p) * 4096;
        float4* o4 = (float4*)o;

        #pragma unroll
        for (int m = 0; m < 4; m++) {
            float v0, v1, v2, v3;
            if (m == 0) {
                if (c < 4) {
                    const float* s0 = &sR[(0 * 8 + p) * 256 + tu * 16 + 4 * c];
                    float sc = pp[0];
                    v0 = sc * s0[0]; v1 = sc * s0[1]; v2 = sc * s0[2]; v3 = sc * s0[3];
                } else {
                    const float* s1 = &sR[(1 * 8 + p) * 256 + tu * 16];
                    v0 = pp[1 + jd0] * s1[vd0];
                    v1 = pp[1 + jd1] * s1[vd1];
                    v2 = pp[1 + jd2] * s1[vd2];
                    v3 = pp[1 + jd3] * s1[vd3];
                }
            } else {
                int u2 = um[m], i = im[m];
                if (c < 4) {
                    const float* s2 = &sR[(2 * 8 + p) * 256 + u2 * 16 + 4 * c];
                    float sc = pp[4 + i];
                    v0 = sc * s2[0]; v1 = sc * s2[1]; v2 = sc * s2[2]; v3 = sc * s2[3];
                } else {
                    const float* s3 = &sR[(3 * 8 + p) * 256 + u2 * 16];
                    const float* s4 = &sR[(4 * 8 + p) * 256 + u2 * 16];
                    const float* s5 = &sR[(5 * 8 + p) * 256 + u2 * 16];
                    const float* pa = pp + 7  + 3 * i;
                    const float* pb = pp + 16 + 3 * i;
                    const float* pc = pp + 25 + 3 * i;
                    v0 = pa[jd0] * s3[vd0] + pb[jd0] * s4[vd0] + pc[jd0] * s5[vd0];
                    v1 = pa[jd1] * s3[vd1] + pb[jd1] * s4[vd1] + pc[jd1] * s5[vd1];
                    v2 = pa[jd2] * s3[vd2] + pb[jd2] * s4[vd2] + pc[jd2] * s5[vd2];
                    v3 = pa[jd3] * s3[vd3] + pb[jd3] * s4[vd3] + pc[jd3] * s5[vd3];
                }
            }
            stg_cs(o4 + m * 256 + t, make_float4(v0, v1, v2, v3));
        }
    }
}

// ===========================================================================
// Host: exact replication of the reference real-3j / norm constants.
// ===========================================================================
static double dfact_(int n) { double r = 1.0; for (int i = 2; i <= n; i++) r *= i; return r; }

static double su2_cg_(int j1, int m1, int j2, int m2, int j3, int m3) {
    if (m3 != m1 + m2) return 0.0;
    int vmin = std::max(std::max(-j1 + j2 + m3, -j1 + m1), 0);
    int vmax = std::min(std::min(j2 + j3 + m1, j3 - j1 + j2), j3 + m3);
    double c = sqrt((2 * j3 + 1) * dfact_(j3 + j1 - j2) * dfact_(j3 - j1 + j2) *
                    dfact_(j1 + j2 - j3) / dfact_(j1 + j2 + j3 + 1)) *
               sqrt(dfact_(j3 + m3) * dfact_(j3 - m3) /
                    (dfact_(j1 + m1) * dfact_(j1 - m1) * dfact_(j2 + m2) * dfact_(j2 - m2)));
    double s = 0.0;
    for (int v = vmin; v <= vmax; v++) {
        double sg = ((v + j2 + m2) & 1) ? -1.0 : 1.0;
        s += sg * dfact_(j2 + j3 + m1 - v) * dfact_(j1 - m1 + v) /
             (dfact_(v) * dfact_(j3 - j1 + j2 - v) * dfact_(j3 + m3 - v) *
              dfact_(v + j1 - j2 - m3));
    }
    return c * s;
}

static void Qmat_(int l, std::complex<double> q[5][5]) {
    for (int i = 0; i < 5; i++) for (int j = 0; j < 5; j++) q[i][j] = 0.0;
    q[l][l] = 1.0;
    double s2 = 1.0 / sqrt(2.0);
    for (int m = 1; m <= l; m++) {
        double pm = (m & 1) ? -1.0 : 1.0;
        q[l + m][l - m] = s2;
        q[l + m][l + m] = pm * s2;
        q[l - m][l - m] = std::complex<double>(0.0, s2);
        q[l - m][l + m] = std::complex<double>(0.0, -pm * s2);
    }
}

static void real3j_(int l1, int l2, int l3, double outc[5][5][5]) {
    int d1 = 2 * l1 + 1, d2 = 2 * l2 + 1, d3 = 2 * l3 + 1;
    double w[5][5][5];
    for (int i = 0; i < 5; i++) for (int j = 0; j < 5; j++) for (int k = 0; k < 5; k++)
        w[i][j][k] = 0.0;
    for (int m1 = -l1; m1 <= l1; m1++)
        for (int m2 = -l2; m2 <= l2; m2++) {
            int m3 = -(m1 + m2);
            if (m3 < -l3 || m3 > l3) continue;
            double sg = ((l1 - l2 + m1 + m2) & 1) ? -1.0 : 1.0;
            w[m1 + l1][m2 + l2][m3 + l3] =
                sg / sqrt((double)(2 * l3 + 1)) * su2_cg_(l1, m1, l2, m2, l3, -m3);
        }
    std::complex<double> q1[5][5], q2[5][5], q3[5][5];
    Qmat_(l1, q1); Qmat_(l2, q2); Qmat_(l3, q3);
    std::complex<double> Cc[5][5][5];
    for (int a = 0; a < d1; a++)
        for (int b = 0; b < d2; b++)
            for (int c = 0; c < d3; c++) {
                std::complex<double> s = 0.0;
                for (int i = 0; i < d1; i++)
                    for (int j = 0; j < d2; j++)
                        for (int k = 0; k < d3; k++)
                            s += q1[a][i] * q2[b][j] * q3[c][k] * w[i][j][k];
                Cc[a][b][c] = s;
            }
    double maxv = 0.0;
    for (int a = 0; a < d1; a++) for (int b = 0; b < d2; b++) for (int c = 0; c < d3; c++)
        maxv = std::max(maxv, std::abs(Cc[a][b][c]));
    std::complex<double> ph = 0.0;
    for (int a = 0; a < d1 && ph == 0.0; a++)
        for (int b = 0; b < d2 && ph == 0.0; b++)
            for (int c = 0; c < d3 && ph == 0.0; c++)
                if (std::abs(Cc[a][b][c]) >= maxv * (1.0 - 1e-9)) ph = Cc[a][b][c];
    for (int i = 0; i < 5; i++) for (int j = 0; j < 5; j++) for (int k = 0; k < 5; k++)
        outc[i][j][k] = 0.0;
    if (std::abs(ph) < 1e-12) {
        for (int a = 0; a < d1; a++) for (int b = 0; b < d2; b++) for (int c = 0; c < d3; c++)
            outc[a][b][c] = Cc[a][b][c].real();
    } else {
        std::complex<double> u = ph / std::abs(ph);
        for (int a = 0; a < d1; a++) for (int b = 0; b < d2; b++) for (int c = 0; c < d3; c++)
            outc[a][b][c] = (Cc[a][b][c] / u).real();
    }
}

extern "C" void kernel_launch(void* const* d_in, const int* in_sizes, int n_in,
                              void* d_out, int out_size) {
    const float* r  = (const float*)d_in[0];
    const float* W1 = (const float*)d_in[1];
    const float* b1 = (const float*)d_in[2];
    const float* W2 = (const float*)d_in[3];
    const float* b2 = (const float*)d_in[4];
    float* out = (float*)d_out;

    Consts C;
    double tmp[5][5][5];
    real3j_(0, 0, 0, tmp); C.cg000 = (float)tmp[0][0][0];
    real3j_(0, 1, 1, tmp);
    for (int j = 0; j < 3; j++) for (int k = 0; k < 3; k++) C.cg011[j][k] = (float)tmp[0][j][k];
    real3j_(1, 0, 1, tmp);
    for (int i = 0; i < 3; i++) for (int k = 0; k < 3; k++) C.cg101[i][k] = (float)tmp[i][0][k];
    real3j_(1, 1, 0, tmp);
    for (int i = 0; i < 3; i++) for (int j = 0; j < 3; j++) C.cg110[i][j] = (float)tmp[i][j][0];
    real3j_(1, 1, 1, tmp);
    for (int i = 0; i < 3; i++) for (int j = 0; j < 3; j++) for (int k = 0; k < 3; k++)
        C.cg111[i][j][k] = (float)tmp[i][j][k];
    real3j_(1, 1, 2, tmp);
    for (int i = 0; i < 3; i++) for (int j = 0; j < 3; j++) for (int k = 0; k < 5; k++)
        C.cg112[i][j][k] = (float)tmp[i][j][k];

    const double fourpi = 4.0 * M_PI;
    double nse[2] = {32.0, 64.0};
    for (int i = 0; i < 2; i++)
        for (int j = 0; j < 2; j++) {
            double li = (j == 0) ? 0.0 : 1.0;
            double lm = sqrt(2.0 * li + 1.0) * sqrt(fourpi);
            C.nrm[i][j][0] = (float)(lm / sqrt(nse[i]));
            C.nrm[i][j][1] = (float)(lm / sqrt(16.0));
        }

    cudaFuncSetAttribute(qm9_fused, cudaFuncAttributeMaxDynamicSharedMemorySize,
                         SMEM_TOTAL);

    permute_w2<<<(64 * NPATH + 255) / 256, 256>>>(W2);
    qm9_fused<<<NBLK, NTHREADS, SMEM_TOTAL>>>(r, W1, b1, b2, out, C);
}